// round 14
// baseline (speedup 1.0000x reference)
#include <cuda_runtime.h>
#include <math.h>
#include <stdint.h>

#define NN   50000
#define E2C  400000
#define EE   800000
#define DINC 512
#define DHC  128
#define CCH  8
#define KITER 5

#define LOG2E 1.4426950408889634f
#define LN2   0.6931471805599453f

// ---------------- scratch (device globals; no allocation allowed) ----------
// NOTE: all log-domain state (logb0, logb, agg, msg) is kept in BASE-2.
__device__ __align__(16) float g_logb0[NN * CCH];
__device__ __align__(16) float g_logb [NN * CCH];
__device__ __align__(16) float g_agg  [NN * CCH];
__device__ __align__(16) float g_msg0 [EE * CCH];
__device__ __align__(16) float g_msg1 [EE * CCH];
__device__ __align__(16) float g_logH [CCH * CCH];

// ---------------- fast math helpers ----------------------------------------
__device__ __forceinline__ float fex2(float x) {
    float r; asm("ex2.approx.ftz.f32 %0, %1;" : "=f"(r) : "f"(x)); return r;
}
__device__ __forceinline__ float flg2(float x) {
    float r; asm("lg2.approx.ftz.f32 %0, %1;" : "=f"(r) : "f"(x)); return r;
}
__device__ __forceinline__ void redv4(float* p, float a, float b, float c, float d) {
    asm volatile("red.global.add.v4.f32 [%0], {%1, %2, %3, %4};"
                 :: "l"(p), "f"(a), "f"(b), "f"(c), "f"(d) : "memory");
}
__device__ __forceinline__ uint32_t f2tf32(float f) {
    uint32_t u; asm("cvt.rna.tf32.f32 %0, %1;" : "=r"(u) : "f"(f)); return u;
}
__device__ __forceinline__ void mma_tf32(float4& d, const uint32_t* a, const uint32_t* b) {
    asm("mma.sync.aligned.m16n8k8.row.col.f32.tf32.tf32.f32 "
        "{%0,%1,%2,%3},{%4,%5,%6,%7},{%8,%9},{%0,%1,%2,%3};"
        : "+f"(d.x), "+f"(d.y), "+f"(d.z), "+f"(d.w)
        : "r"(a[0]), "r"(a[1]), "r"(a[2]), "r"(a[3]), "r"(b[0]), "r"(b[1]));
}

// ---------------- MLP: logb0_2 = log2_softmax(relu(x@W1+b1)@W2+b2) ---------
// GEMM1 on tensor cores (tf32, 3xTF32 split). Block 64 rows x 128 cols, K
// chunks of 16, 8 warps (32x32 each). Fragment-pair-packed smem layouts so
// all fragment loads are LDS.64:
//   A: uint2 slot j of k-octet = (A[r][k8+j], A[r][k8+j+4]), pitch 24 words.
//   B: uint2 at [ks*4+tg][col]  = (B[k=8ks+tg][col], B[k=8ks+tg+4][col]),
//      pitch 132 uint2 (banks 8tg+2g+{0,1}: conflict-free).
#define BM 64
#define BKC 16
#define APITCH 24                 // words per A row (16 data + 8 pad)
#define BPP 132                   // uint2 pitch per B k-pair row
#define NKCH (DINC / BKC)         // 32

#define OFF_AHI 0
#define OFF_ALO (BM * APITCH)                    // 1536
#define OFF_BHI (2 * BM * APITCH)                // 3072 (uint2 region)
#define OFF_BLO (OFF_BHI + 2 * 8 * BPP)          // 3072 + 2112 = 5184
#define PH1_WORDS (OFF_BLO + 2 * 8 * BPP)        // 7296
#define HS_WORDS (BM * 129)                      // 8256
#define BUF_WORDS (HS_WORDS > PH1_WORDS ? HS_WORDS : PH1_WORDS)

__global__ void __launch_bounds__(256) mlp_kernel(const float* __restrict__ x,
                           const float* __restrict__ W1,
                           const float* __restrict__ b1,
                           const float* __restrict__ W2,
                           const float* __restrict__ b2) {
    __shared__ __align__(16) uint32_t buf[BUF_WORDS];
    __shared__ __align__(16) float W2s[DHC * CCH];
    __shared__ float b1s[DHC];

    uint32_t* Ahi = buf + OFF_AHI;
    uint32_t* Alo = buf + OFF_ALO;
    uint2*    Bhi2 = (uint2*)(buf + OFF_BHI);
    uint2*    Blo2 = (uint2*)(buf + OFF_BLO);
    float*    Hs  = (float*)buf;     // phase 2: Hs[r][k] pitch 129

    const int tid = threadIdx.x;
    const int wid = tid >> 5;
    const int lane = tid & 31;
    const int block_row = blockIdx.x * BM;

#pragma unroll
    for (int i = 0; i < 4; i++) W2s[tid + i * 256] = W2[tid + i * 256];
    if (tid < DHC) b1s[tid] = b1[tid];

    // A global load: 64 rows x 16 k, 1 float4/thread
    const int arow = tid >> 2;
    const int aq   = (tid & 3) * 4;            // 0,4,8,12
    const int gr   = block_row + arow;
    const bool avalid = (gr < NN);
    // pair-packed store base: k-octet = aq>>3, parity = (aq>>2)&1
    const int abase = arow * APITCH + (aq >> 3) * 8 + ((aq >> 2) & 1);

    // B global load: warp w loads W1 rows (8*(w>>2) + (w&3)) and +4, 4 cols
    const int brow = tid >> 5;                 // 0..7 == ks*4+tg (tp index)
    const int bks  = brow >> 2;
    const int btg  = brow & 3;
    const int bcol = (tid & 31) * 4;
    const int br0  = bks * 8 + btg;            // k row of bx0 (bx1 = +4)

    const int m0 = (wid & 1) * 32;
    const int n0 = (wid >> 1) * 32;
    const int g  = lane >> 2;
    const int tg = lane & 3;

    float4 acc[2][4];
#pragma unroll
    for (int mi = 0; mi < 2; mi++)
#pragma unroll
        for (int ni = 0; ni < 4; ni++) acc[mi][ni] = make_float4(0.f, 0.f, 0.f, 0.f);

    float4 ax = make_float4(0.f, 0.f, 0.f, 0.f), bx0, bx1;
    if (avalid) ax = *(const float4*)&x[(size_t)gr * DINC + aq];
    bx0 = *(const float4*)&W1[(size_t)br0 * DHC + bcol];
    bx1 = *(const float4*)&W1[(size_t)(br0 + 4) * DHC + bcol];

    for (int c = 0; c < NKCH; c++) {
        // A: split + pair-packed scalar stores
        {
            float av[4] = {ax.x, ax.y, ax.z, ax.w};
#pragma unroll
            for (int j = 0; j < 4; j++) {
                uint32_t h = f2tf32(av[j]);
                Ahi[abase + 2 * j] = h;
                Alo[abase + 2 * j] = f2tf32(av[j] - __uint_as_float(h));
            }
        }
        // B: split + pair-packed uint4 stores (2 cols per uint4)
        {
            float bv0[4] = {bx0.x, bx0.y, bx0.z, bx0.w};
            float bv1[4] = {bx1.x, bx1.y, bx1.z, bx1.w};
            uint32_t h0[4], l0[4], h1[4], l1[4];
#pragma unroll
            for (int j = 0; j < 4; j++) {
                h0[j] = f2tf32(bv0[j]); l0[j] = f2tf32(bv0[j] - __uint_as_float(h0[j]));
                h1[j] = f2tf32(bv1[j]); l1[j] = f2tf32(bv1[j] - __uint_as_float(h1[j]));
            }
            uint2* bh = &Bhi2[brow * BPP + bcol];
            uint2* bl = &Blo2[brow * BPP + bcol];
            *(uint4*)(bh)     = make_uint4(h0[0], h1[0], h0[1], h1[1]);
            *(uint4*)(bh + 2) = make_uint4(h0[2], h1[2], h0[3], h1[3]);
            *(uint4*)(bl)     = make_uint4(l0[0], l1[0], l0[1], l1[1]);
            *(uint4*)(bl + 2) = make_uint4(l0[2], l1[2], l0[3], l1[3]);
        }
        __syncthreads();

        if (c + 1 < NKCH) {
            int k0 = (c + 1) * BKC;
            if (avalid) ax = *(const float4*)&x[(size_t)gr * DINC + k0 + aq];
            bx0 = *(const float4*)&W1[(size_t)(k0 + br0) * DHC + bcol];
            bx1 = *(const float4*)&W1[(size_t)(k0 + br0 + 4) * DHC + bcol];
        }

#pragma unroll
        for (int ks = 0; ks < 2; ks++) {
            // A fragments: LDS.64 pairs
            uint32_t ah[2][4], al[2][4];
#pragma unroll
            for (int mi = 0; mi < 2; mi++) {
                int idx = (m0 + 16 * mi + g) * (APITCH / 2) + ks * 4 + tg;
                uint2 q0 = ((const uint2*)Ahi)[idx];
                uint2 q1 = ((const uint2*)Ahi)[idx + 8 * (APITCH / 2)];
                ah[mi][0] = q0.x; ah[mi][1] = q1.x; ah[mi][2] = q0.y; ah[mi][3] = q1.y;
                uint2 p0 = ((const uint2*)Alo)[idx];
                uint2 p1 = ((const uint2*)Alo)[idx + 8 * (APITCH / 2)];
                al[mi][0] = p0.x; al[mi][1] = p1.x; al[mi][2] = p0.y; al[mi][3] = p1.y;
            }
            // B fragments: LDS.64 pairs
            uint32_t bh[4][2], bl[4][2];
#pragma unroll
            for (int ni = 0; ni < 4; ni++) {
                int bidx = (ks * 4 + tg) * BPP + n0 + 8 * ni + g;
                uint2 h2 = Bhi2[bidx];
                uint2 l2 = Blo2[bidx];
                bh[ni][0] = h2.x; bh[ni][1] = h2.y;
                bl[ni][0] = l2.x; bl[ni][1] = l2.y;
            }
#pragma unroll
            for (int mi = 0; mi < 2; mi++)
#pragma unroll
                for (int ni = 0; ni < 4; ni++) {
                    mma_tf32(acc[mi][ni], ah[mi], bh[ni]);
                    mma_tf32(acc[mi][ni], ah[mi], bl[ni]);
                    mma_tf32(acc[mi][ni], al[mi], bh[ni]);
                }
        }
        __syncthreads();
    }

    // epilogue: h = relu(acc + b1) -> Hs
#pragma unroll
    for (int mi = 0; mi < 2; mi++) {
#pragma unroll
        for (int ni = 0; ni < 4; ni++) {
            int row = m0 + 16 * mi + g;
            int col = n0 + 8 * ni + 2 * tg;
            float bb0 = b1s[col], bb1 = b1s[col + 1];
            float v0 = acc[mi][ni].x + bb0, v1 = acc[mi][ni].y + bb1;
            float v2 = acc[mi][ni].z + bb0, v3 = acc[mi][ni].w + bb1;
            Hs[row * 129 + col]           = v0 > 0.f ? v0 : 0.f;
            Hs[row * 129 + col + 1]       = v1 > 0.f ? v1 : 0.f;
            Hs[(row + 8) * 129 + col]     = v2 > 0.f ? v2 : 0.f;
            Hs[(row + 8) * 129 + col + 1] = v3 > 0.f ? v3 : 0.f;
        }
    }
    __syncthreads();

    // second layer + BASE-2 log_softmax: 4 threads per row (k-split x ch-split)
    {
        int row = tid >> 2;
        int q   = tid & 3;
        int ch0 = (q & 1) * 4;
        int kh  = (q >> 1) * 64;
        int grr = block_row + row;
        if (grr < NN) {
            float lg[4] = {0.f, 0.f, 0.f, 0.f};
            for (int k = kh; k < kh + 64; k++) {
                float h = Hs[row * 129 + k];
                const float4 w4 = *(const float4*)&W2s[k * CCH + ch0];
                lg[0] = fmaf(h, w4.x, lg[0]);
                lg[1] = fmaf(h, w4.y, lg[1]);
                lg[2] = fmaf(h, w4.z, lg[2]);
                lg[3] = fmaf(h, w4.w, lg[3]);
            }
            // combine k-halves (partner lane = lane^2, same row)
#pragma unroll
            for (int cc = 0; cc < 4; cc++)
                lg[cc] += __shfl_xor_sync(0xFFFFFFFF, lg[cc], 2);
#pragma unroll
            for (int cc = 0; cc < 4; cc++) lg[cc] += b2[ch0 + cc];

            float mx = fmaxf(fmaxf(lg[0], lg[1]), fmaxf(lg[2], lg[3]));
            mx = fmaxf(mx, __shfl_xor_sync(0xFFFFFFFF, mx, 1));
            float y2[4];
            float s = 0.f;
#pragma unroll
            for (int cc = 0; cc < 4; cc++) {
                y2[cc] = (lg[cc] - mx) * LOG2E;
                s += fex2(y2[cc]);
            }
            s += __shfl_xor_sync(0xFFFFFFFF, s, 1);
            float lse2 = flg2(s);
            if (q < 2) {
#pragma unroll
                for (int cc = 0; cc < 4; cc++)
                    g_logb0[grr * CCH + ch0 + cc] = y2[cc] - lse2;   // base-2
            }
        }
    }
}

// ---------------- init: zero agg + logH = logsigmoid(param + param^T) ------
__global__ void init_kernel(const float* __restrict__ param) {
    int i = blockIdx.x * blockDim.x + threadIdx.x;
    if (i < NN * CCH) g_agg[i] = 0.f;
    if (blockIdx.x == 0 && threadIdx.x < CCH * CCH) {
        int t = threadIdx.x;
        int r = t >> 3, c = t & 7;
        float z = param[r * CCH + c] + param[c * CCH + r];
        float a = fabsf(z);
        g_logH[t] = fminf(z, 0.f) - log1pf(expf(-a));
    }
}

// ---------------- edge kernel: one thread per UNDIRECTED edge --------------
// Base-2 domain; unnormalized messages (per-edge shifts cancel exactly under
// per-node belief normalization). G symmetric -> 36 exp2 instead of 64.
__global__ void __launch_bounds__(256, 5)
edge_kernel(const int* __restrict__ srcp,
            const int* __restrict__ dstp,
            const float* __restrict__ wp,
            int iter) {
    __shared__ float H2s[CCH * CCH];   // logH * log2(e)
    if (threadIdx.x < CCH * CCH) H2s[threadIdx.x] = g_logH[threadIdx.x] * LOG2E;
    __syncthreads();

    int u = blockIdx.x * blockDim.x + threadIdx.x;
    if (u >= E2C) return;

    const float* logb = (iter == 0) ? g_logb0 : g_logb;
    const float* prev = (iter & 1) ? g_msg0 : g_msg1;
    float* cur = (iter & 1) ? g_msg1 : g_msg0;

    int s = srcp[u];
    int d = dstp[u];
    float w = wp[u];

    float xs[8], xd[8];
    {
        const float4* bp = (const float4*)(logb + (size_t)s * CCH);
        float4 v0 = bp[0], v1 = bp[1];
        xs[0]=v0.x; xs[1]=v0.y; xs[2]=v0.z; xs[3]=v0.w;
        xs[4]=v1.x; xs[5]=v1.y; xs[6]=v1.z; xs[7]=v1.w;
        const float4* bq = (const float4*)(logb + (size_t)d * CCH);
        float4 u0 = bq[0], u1 = bq[1];
        xd[0]=u0.x; xd[1]=u0.y; xd[2]=u0.z; xd[3]=u0.w;
        xd[4]=u1.x; xd[5]=u1.y; xd[6]=u1.z; xd[7]=u1.w;
    }
    if (iter != 0) {
        const float4* pf = (const float4*)(prev + (size_t)(u + E2C) * CCH);
        float4 p0 = pf[0], p1 = pf[1];
        xs[0]-=p0.x; xs[1]-=p0.y; xs[2]-=p0.z; xs[3]-=p0.w;
        xs[4]-=p1.x; xs[5]-=p1.y; xs[6]-=p1.z; xs[7]-=p1.w;
        const float4* pb = (const float4*)(prev + (size_t)u * CCH);
        float4 q0 = pb[0], q1 = pb[1];
        xd[0]-=q0.x; xd[1]-=q0.y; xd[2]-=q0.z; xd[3]-=q0.w;
        xd[4]-=q1.x; xd[5]-=q1.y; xd[6]-=q1.z; xd[7]-=q1.w;
    }

    float mxs = xs[0], mxd = xd[0];
#pragma unroll
    for (int c = 1; c < 8; c++) { mxs = fmaxf(mxs, xs[c]); mxd = fmaxf(mxd, xd[c]); }

    float Ef[8], Eb[8];
#pragma unroll
    for (int c = 0; c < 8; c++) {
        Ef[c] = fex2(xs[c] - mxs);
        Eb[c] = fex2(xd[c] - mxd);
    }

    float Sf[8], Sb[8];
#pragma unroll
    for (int c = 0; c < 8; c++) {
        float gg = fex2(w * H2s[c * 8 + c]);
        Sf[c] = Ef[c] * gg;
        Sb[c] = Eb[c] * gg;
    }
#pragma unroll
    for (int c = 1; c < 8; c++) {
#pragma unroll
        for (int cp = 0; cp < c; cp++) {
            float gg = fex2(w * H2s[cp * 8 + c]);
            Sf[c]  = fmaf(Ef[cp], gg, Sf[c]);
            Sf[cp] = fmaf(Ef[c],  gg, Sf[cp]);
            Sb[c]  = fmaf(Eb[cp], gg, Sb[c]);
            Sb[cp] = fmaf(Eb[c],  gg, Sb[cp]);
        }
    }

    float mf[8], mb[8];
#pragma unroll
    for (int c = 0; c < 8; c++) {
        mf[c] = flg2(Sf[c]) + mxs;
        mb[c] = flg2(Sb[c]) + mxd;
    }

    float4* cf = (float4*)(cur + (size_t)u * CCH);
    cf[0] = make_float4(mf[0], mf[1], mf[2], mf[3]);
    cf[1] = make_float4(mf[4], mf[5], mf[6], mf[7]);
    float4* cb = (float4*)(cur + (size_t)(u + E2C) * CCH);
    cb[0] = make_float4(mb[0], mb[1], mb[2], mb[3]);
    cb[1] = make_float4(mb[4], mb[5], mb[6], mb[7]);

    float* agd = g_agg + (size_t)d * CCH;
    redv4(agd,     mf[0], mf[1], mf[2], mf[3]);
    redv4(agd + 4, mf[4], mf[5], mf[6], mf[7]);
    float* ags = g_agg + (size_t)s * CCH;
    redv4(ags,     mb[0], mb[1], mb[2], mb[3]);
    redv4(ags + 4, mb[4], mb[5], mb[6], mb[7]);
}

// ---------------- node kernel: normalize beliefs (base-2), reset agg -------
__global__ void node_kernel(float* __restrict__ outp, int final_iter) {
    int i = blockIdx.x * blockDim.x + threadIdx.x;
    if (i >= NN) return;

    const float4* b0 = (const float4*)(g_logb0 + (size_t)i * CCH);
    float4* ag = (float4*)(g_agg + (size_t)i * CCH);
    float4 a0 = b0[0], a1 = b0[1];
    float4 g0 = ag[0], g1 = ag[1];

    float v[8] = {a0.x + g0.x, a0.y + g0.y, a0.z + g0.z, a0.w + g0.w,
                  a1.x + g1.x, a1.y + g1.y, a1.z + g1.z, a1.w + g1.w};

    float mx = v[0];
#pragma unroll
    for (int c = 1; c < 8; c++) mx = fmaxf(mx, v[c]);
    float sacc = 0.f;
#pragma unroll
    for (int c = 0; c < 8; c++) sacc += fex2(v[c] - mx);
    float lse2 = mx + flg2(sacc);

    if (final_iter) {
        float4* o4 = (float4*)(outp + (size_t)i * CCH);
        o4[0] = make_float4((v[0]-lse2)*LN2, (v[1]-lse2)*LN2,
                            (v[2]-lse2)*LN2, (v[3]-lse2)*LN2);
        o4[1] = make_float4((v[4]-lse2)*LN2, (v[5]-lse2)*LN2,
                            (v[6]-lse2)*LN2, (v[7]-lse2)*LN2);
    } else {
        float4* o4 = (float4*)(g_logb + (size_t)i * CCH);
        o4[0] = make_float4(v[0]-lse2, v[1]-lse2, v[2]-lse2, v[3]-lse2);
        o4[1] = make_float4(v[4]-lse2, v[5]-lse2, v[6]-lse2, v[7]-lse2);
    }

    float4 z = make_float4(0.f, 0.f, 0.f, 0.f);
    ag[0] = z; ag[1] = z;
}

// ---------------- launch ---------------------------------------------------
extern "C" void kernel_launch(void* const* d_in, const int* in_sizes, int n_in,
                              void* d_out, int out_size) {
    const float* x     = (const float*)d_in[0];
    const int*   ei    = (const int*)  d_in[1];
    const float* ew    = (const float*)d_in[2];
    const float* W1    = (const float*)d_in[4];
    const float* b1    = (const float*)d_in[5];
    const float* W2    = (const float*)d_in[6];
    const float* b2    = (const float*)d_in[7];
    const float* param = (const float*)d_in[8];
    const int* srcp = ei;          // first E2C entries are the undirected srcs
    const int* dstp = ei + EE;     // dst row; first E2C entries pair with srcp
    float* outp = (float*)d_out;

    mlp_kernel<<<(NN + BM - 1) / BM, 256>>>(x, W1, b1, W2, b2);
    init_kernel<<<(NN * CCH + 255) / 256, 256>>>(param);

    for (int it = 0; it < KITER; it++) {
        edge_kernel<<<(E2C + 255) / 256, 256>>>(srcp, dstp, ew, it);
        node_kernel<<<(NN + 255) / 256, 256>>>(outp, it == KITER - 1);
    }
}

// round 16
// speedup vs baseline: 1.1844x; 1.1844x over previous
#include <cuda_runtime.h>
#include <math.h>
#include <stdint.h>

#define NN   50000
#define E2C  400000
#define EE   800000
#define DINC 512
#define DHC  128
#define CCH  8
#define KITER 5

#define LOG2E 1.4426950408889634f
#define LN2   0.6931471805599453f

// ---------------- scratch (device globals; no allocation allowed) ----------
// NOTE: all log-domain state (logb0, logb, agg, msg) is kept in BASE-2.
__device__ __align__(16) float g_logb0[NN * CCH];
__device__ __align__(16) float g_logb [NN * CCH];
__device__ __align__(16) float g_agg  [NN * CCH];
__device__ __align__(16) float g_msg0 [EE * CCH];
__device__ __align__(16) float g_msg1 [EE * CCH];
__device__ __align__(16) float g_logH [CCH * CCH];

// ---------------- fast math helpers ----------------------------------------
__device__ __forceinline__ float fex2(float x) {
    float r; asm("ex2.approx.ftz.f32 %0, %1;" : "=f"(r) : "f"(x)); return r;
}
__device__ __forceinline__ float flg2(float x) {
    float r; asm("lg2.approx.ftz.f32 %0, %1;" : "=f"(r) : "f"(x)); return r;
}
__device__ __forceinline__ void redv4(float* p, float a, float b, float c, float d) {
    asm volatile("red.global.add.v4.f32 [%0], {%1, %2, %3, %4};"
                 :: "l"(p), "f"(a), "f"(b), "f"(c), "f"(d) : "memory");
}
__device__ __forceinline__ uint32_t f2tf32(float f) {
    uint32_t u; asm("cvt.rna.tf32.f32 %0, %1;" : "=r"(u) : "f"(f)); return u;
}
__device__ __forceinline__ void mma_tf32(float4& d, const uint32_t* a, const uint32_t* b) {
    asm("mma.sync.aligned.m16n8k8.row.col.f32.tf32.tf32.f32 "
        "{%0,%1,%2,%3},{%4,%5,%6,%7},{%8,%9},{%0,%1,%2,%3};"
        : "+f"(d.x), "+f"(d.y), "+f"(d.z), "+f"(d.w)
        : "r"(a[0]), "r"(a[1]), "r"(a[2]), "r"(a[3]), "r"(b[0]), "r"(b[1]));
}

// ---------------- MLP: logb0_2 = log2_softmax(relu(x@W1+b1)@W2+b2) ---------
// GEMM1 on tensor cores (tf32, 3xTF32 split). Block 64 rows x 128 cols (full
// DH), K chunks of 16, 8 warps (32x32 each). A and B staged through smem
// (APAD=20, BPAD=136 -> conflict-free fragment loads). [R12 proven version]
#define BM 64
#define BKC 16
#define APAD 20
#define BPAD 136
#define NKCH (DINC / BKC)   // 32

#define OFF_AHI 0
#define OFF_ALO (OFF_AHI + BM * APAD)            // 1280
#define OFF_BHI (OFF_ALO + BM * APAD)            // 2560
#define OFF_BLO (OFF_BHI + BKC * BPAD)           // 4736
#define PH1_WORDS (OFF_BLO + BKC * BPAD)         // 6912
#define HS_WORDS (BM * 129)                      // 8256
#define BUF_WORDS (HS_WORDS > PH1_WORDS ? HS_WORDS : PH1_WORDS)

__global__ void __launch_bounds__(256) mlp_kernel(const float* __restrict__ x,
                           const float* __restrict__ W1,
                           const float* __restrict__ b1,
                           const float* __restrict__ W2,
                           const float* __restrict__ b2) {
    __shared__ __align__(16) uint32_t buf[BUF_WORDS];
    __shared__ __align__(16) float W2s[DHC * CCH];
    __shared__ float b1s[DHC];

    uint32_t* Ahi = buf + OFF_AHI;
    uint32_t* Alo = buf + OFF_ALO;
    uint32_t* Bhi = buf + OFF_BHI;
    uint32_t* Blo = buf + OFF_BLO;
    float*    Hs  = (float*)buf;     // phase 2: Hs[r][k] pitch 129

    const int tid = threadIdx.x;
    const int wid = tid >> 5;
    const int lane = tid & 31;
    const int block_row = blockIdx.x * BM;

#pragma unroll
    for (int i = 0; i < 4; i++) W2s[tid + i * 256] = W2[tid + i * 256];
    if (tid < DHC) b1s[tid] = b1[tid];

    const int arow = tid >> 2;
    const int aq   = (tid & 3) * 4;
    const int brow = tid >> 5;
    const int bcol = (tid & 31) * 4;
    const int gr   = block_row + arow;
    const bool avalid = (gr < NN);

    const int m0 = (wid & 1) * 32;
    const int n0 = (wid >> 1) * 32;
    const int g  = lane >> 2;
    const int tg = lane & 3;

    float4 acc[2][4];
#pragma unroll
    for (int mi = 0; mi < 2; mi++)
#pragma unroll
        for (int ni = 0; ni < 4; ni++) acc[mi][ni] = make_float4(0.f, 0.f, 0.f, 0.f);

    float4 ax = make_float4(0.f, 0.f, 0.f, 0.f), bx0, bx1;
    if (avalid) ax = *(const float4*)&x[(size_t)gr * DINC + aq];
    bx0 = *(const float4*)&W1[(size_t)brow * DHC + bcol];
    bx1 = *(const float4*)&W1[(size_t)(brow + 8) * DHC + bcol];

    for (int c = 0; c < NKCH; c++) {
        {
            float av[4] = {ax.x, ax.y, ax.z, ax.w};
            uint32_t hi4[4], lo4[4];
#pragma unroll
            for (int j = 0; j < 4; j++) {
                hi4[j] = f2tf32(av[j]);
                lo4[j] = f2tf32(av[j] - __uint_as_float(hi4[j]));
            }
            *(uint4*)&Ahi[arow * APAD + aq] = *(uint4*)hi4;
            *(uint4*)&Alo[arow * APAD + aq] = *(uint4*)lo4;

            float bv0[4] = {bx0.x, bx0.y, bx0.z, bx0.w};
            float bv1[4] = {bx1.x, bx1.y, bx1.z, bx1.w};
            uint32_t h0[4], l0[4], h1[4], l1[4];
#pragma unroll
            for (int j = 0; j < 4; j++) {
                h0[j] = f2tf32(bv0[j]); l0[j] = f2tf32(bv0[j] - __uint_as_float(h0[j]));
                h1[j] = f2tf32(bv1[j]); l1[j] = f2tf32(bv1[j] - __uint_as_float(h1[j]));
            }
            *(uint4*)&Bhi[brow * BPAD + bcol] = *(uint4*)h0;
            *(uint4*)&Blo[brow * BPAD + bcol] = *(uint4*)l0;
            *(uint4*)&Bhi[(brow + 8) * BPAD + bcol] = *(uint4*)h1;
            *(uint4*)&Blo[(brow + 8) * BPAD + bcol] = *(uint4*)l1;
        }
        __syncthreads();

        if (c + 1 < NKCH) {
            int k0 = (c + 1) * BKC;
            if (avalid) ax = *(const float4*)&x[(size_t)gr * DINC + k0 + aq];
            bx0 = *(const float4*)&W1[(size_t)(k0 + brow) * DHC + bcol];
            bx1 = *(const float4*)&W1[(size_t)(k0 + brow + 8) * DHC + bcol];
        }

#pragma unroll
        for (int ks = 0; ks < BKC; ks += 8) {
            uint32_t ah[2][4], al[2][4];
#pragma unroll
            for (int mi = 0; mi < 2; mi++) {
                int r0 = (m0 + 16 * mi + g) * APAD + ks + tg;
                int r1 = (m0 + 16 * mi + g + 8) * APAD + ks + tg;
                ah[mi][0] = Ahi[r0];     ah[mi][1] = Ahi[r1];
                ah[mi][2] = Ahi[r0 + 4]; ah[mi][3] = Ahi[r1 + 4];
                al[mi][0] = Alo[r0];     al[mi][1] = Alo[r1];
                al[mi][2] = Alo[r0 + 4]; al[mi][3] = Alo[r1 + 4];
            }
            uint32_t bh[4][2], bl[4][2];
#pragma unroll
            for (int ni = 0; ni < 4; ni++) {
                int col = n0 + 8 * ni + g;
                bh[ni][0] = Bhi[(ks + tg) * BPAD + col];
                bh[ni][1] = Bhi[(ks + tg + 4) * BPAD + col];
                bl[ni][0] = Blo[(ks + tg) * BPAD + col];
                bl[ni][1] = Blo[(ks + tg + 4) * BPAD + col];
            }
#pragma unroll
            for (int mi = 0; mi < 2; mi++)
#pragma unroll
                for (int ni = 0; ni < 4; ni++) {
                    mma_tf32(acc[mi][ni], ah[mi], bh[ni]);
                    mma_tf32(acc[mi][ni], ah[mi], bl[ni]);
                    mma_tf32(acc[mi][ni], al[mi], bh[ni]);
                }
        }
        __syncthreads();
    }

    // epilogue: h = relu(acc + b1) -> Hs
#pragma unroll
    for (int mi = 0; mi < 2; mi++) {
#pragma unroll
        for (int ni = 0; ni < 4; ni++) {
            int row = m0 + 16 * mi + g;
            int col = n0 + 8 * ni + 2 * tg;
            float bb0 = b1s[col], bb1 = b1s[col + 1];
            float v0 = acc[mi][ni].x + bb0, v1 = acc[mi][ni].y + bb1;
            float v2 = acc[mi][ni].z + bb0, v3 = acc[mi][ni].w + bb1;
            Hs[row * 129 + col]           = v0 > 0.f ? v0 : 0.f;
            Hs[row * 129 + col + 1]       = v1 > 0.f ? v1 : 0.f;
            Hs[(row + 8) * 129 + col]     = v2 > 0.f ? v2 : 0.f;
            Hs[(row + 8) * 129 + col + 1] = v3 > 0.f ? v3 : 0.f;
        }
    }
    __syncthreads();

    // second layer + BASE-2 log_softmax: 2 threads per row, 4 channels each
    if (tid < 2 * BM) {
        int row = tid >> 1;
        int ch0 = (tid & 1) * 4;
        int grr = block_row + row;
        if (grr < NN) {
            float lg[4] = {b2[ch0], b2[ch0 + 1], b2[ch0 + 2], b2[ch0 + 3]};
            for (int k = 0; k < DHC; k++) {
                float h = Hs[row * 129 + k];
                const float4 w4 = *(const float4*)&W2s[k * CCH + ch0];
                lg[0] = fmaf(h, w4.x, lg[0]);
                lg[1] = fmaf(h, w4.y, lg[1]);
                lg[2] = fmaf(h, w4.z, lg[2]);
                lg[3] = fmaf(h, w4.w, lg[3]);
            }
            float mx = fmaxf(fmaxf(lg[0], lg[1]), fmaxf(lg[2], lg[3]));
            mx = fmaxf(mx, __shfl_xor_sync(0xFFFFFFFF, mx, 1));
            float y2[4];
            float s = 0.f;
#pragma unroll
            for (int cc = 0; cc < 4; cc++) {
                y2[cc] = (lg[cc] - mx) * LOG2E;
                s += fex2(y2[cc]);
            }
            s += __shfl_xor_sync(0xFFFFFFFF, s, 1);
            float lse2 = flg2(s);
#pragma unroll
            for (int cc = 0; cc < 4; cc++)
                g_logb0[grr * CCH + ch0 + cc] = y2[cc] - lse2;   // base-2
        }
    }
}

// ---------------- init: zero agg + logH = logsigmoid(param + param^T) ------
__global__ void init_kernel(const float* __restrict__ param) {
    int i = blockIdx.x * blockDim.x + threadIdx.x;
    if (i < NN * CCH) g_agg[i] = 0.f;
    if (blockIdx.x == 0 && threadIdx.x < CCH * CCH) {
        int t = threadIdx.x;
        int r = t >> 3, c = t & 7;
        float z = param[r * CCH + c] + param[c * CCH + r];
        float a = fabsf(z);
        g_logH[t] = fminf(z, 0.f) - log1pf(expf(-a));
    }
}

// ---------------- edge kernel: one thread per UNDIRECTED edge --------------
// Base-2 domain; unnormalized messages (per-edge shifts cancel exactly under
// per-node belief normalization). G symmetric -> 36 exp2 instead of 64.
// Block=128: 9 blocks/SM at 56 regs -> 1152 threads/SM vs 1024 with 256.
__global__ void edge_kernel(const int* __restrict__ srcp,
                            const int* __restrict__ dstp,
                            const float* __restrict__ wp,
                            int iter) {
    __shared__ float H2s[CCH * CCH];   // logH * log2(e)
    if (threadIdx.x < CCH * CCH) H2s[threadIdx.x] = g_logH[threadIdx.x] * LOG2E;
    __syncthreads();

    int u = blockIdx.x * blockDim.x + threadIdx.x;
    if (u >= E2C) return;

    const float* logb = (iter == 0) ? g_logb0 : g_logb;
    const float* prev = (iter & 1) ? g_msg0 : g_msg1;
    float* cur = (iter & 1) ? g_msg1 : g_msg0;

    int s = srcp[u];
    int d = dstp[u];
    float w = wp[u];

    float xs[8], xd[8];
    {
        const float4* bp = (const float4*)(logb + (size_t)s * CCH);
        float4 v0 = bp[0], v1 = bp[1];
        xs[0]=v0.x; xs[1]=v0.y; xs[2]=v0.z; xs[3]=v0.w;
        xs[4]=v1.x; xs[5]=v1.y; xs[6]=v1.z; xs[7]=v1.w;
        const float4* bq = (const float4*)(logb + (size_t)d * CCH);
        float4 u0 = bq[0], u1 = bq[1];
        xd[0]=u0.x; xd[1]=u0.y; xd[2]=u0.z; xd[3]=u0.w;
        xd[4]=u1.x; xd[5]=u1.y; xd[6]=u1.z; xd[7]=u1.w;
    }
    if (iter != 0) {
        const float4* pf = (const float4*)(prev + (size_t)(u + E2C) * CCH);
        float4 p0 = pf[0], p1 = pf[1];
        xs[0]-=p0.x; xs[1]-=p0.y; xs[2]-=p0.z; xs[3]-=p0.w;
        xs[4]-=p1.x; xs[5]-=p1.y; xs[6]-=p1.z; xs[7]-=p1.w;
        const float4* pb = (const float4*)(prev + (size_t)u * CCH);
        float4 q0 = pb[0], q1 = pb[1];
        xd[0]-=q0.x; xd[1]-=q0.y; xd[2]-=q0.z; xd[3]-=q0.w;
        xd[4]-=q1.x; xd[5]-=q1.y; xd[6]-=q1.z; xd[7]-=q1.w;
    }

    float mxs = xs[0], mxd = xd[0];
#pragma unroll
    for (int c = 1; c < 8; c++) { mxs = fmaxf(mxs, xs[c]); mxd = fmaxf(mxd, xd[c]); }

    float Ef[8], Eb[8];
#pragma unroll
    for (int c = 0; c < 8; c++) {
        Ef[c] = fex2(xs[c] - mxs);
        Eb[c] = fex2(xd[c] - mxd);
    }

    float Sf[8], Sb[8];
#pragma unroll
    for (int c = 0; c < 8; c++) {
        float gg = fex2(w * H2s[c * 8 + c]);
        Sf[c] = Ef[c] * gg;
        Sb[c] = Eb[c] * gg;
    }
#pragma unroll
    for (int c = 1; c < 8; c++) {
#pragma unroll
        for (int cp = 0; cp < c; cp++) {
            float gg = fex2(w * H2s[cp * 8 + c]);
            Sf[c]  = fmaf(Ef[cp], gg, Sf[c]);
            Sf[cp] = fmaf(Ef[c],  gg, Sf[cp]);
            Sb[c]  = fmaf(Eb[cp], gg, Sb[c]);
            Sb[cp] = fmaf(Eb[c],  gg, Sb[cp]);
        }
    }

    float mf[8], mb[8];
#pragma unroll
    for (int c = 0; c < 8; c++) {
        mf[c] = flg2(Sf[c]) + mxs;
        mb[c] = flg2(Sb[c]) + mxd;
    }

    float4* cf = (float4*)(cur + (size_t)u * CCH);
    cf[0] = make_float4(mf[0], mf[1], mf[2], mf[3]);
    cf[1] = make_float4(mf[4], mf[5], mf[6], mf[7]);
    float4* cb = (float4*)(cur + (size_t)(u + E2C) * CCH);
    cb[0] = make_float4(mb[0], mb[1], mb[2], mb[3]);
    cb[1] = make_float4(mb[4], mb[5], mb[6], mb[7]);

    float* agd = g_agg + (size_t)d * CCH;
    redv4(agd,     mf[0], mf[1], mf[2], mf[3]);
    redv4(agd + 4, mf[4], mf[5], mf[6], mf[7]);
    float* ags = g_agg + (size_t)s * CCH;
    redv4(ags,     mb[0], mb[1], mb[2], mb[3]);
    redv4(ags + 4, mb[4], mb[5], mb[6], mb[7]);
}

// ---------------- node kernel: normalize beliefs (base-2), reset agg -------
__global__ void node_kernel(float* __restrict__ outp, int final_iter) {
    int i = blockIdx.x * blockDim.x + threadIdx.x;
    if (i >= NN) return;

    const float4* b0 = (const float4*)(g_logb0 + (size_t)i * CCH);
    float4* ag = (float4*)(g_agg + (size_t)i * CCH);
    float4 a0 = b0[0], a1 = b0[1];
    float4 g0 = ag[0], g1 = ag[1];

    float v[8] = {a0.x + g0.x, a0.y + g0.y, a0.z + g0.z, a0.w + g0.w,
                  a1.x + g1.x, a1.y + g1.y, a1.z + g1.z, a1.w + g1.w};

    float mx = v[0];
#pragma unroll
    for (int c = 1; c < 8; c++) mx = fmaxf(mx, v[c]);
    float sacc = 0.f;
#pragma unroll
    for (int c = 0; c < 8; c++) sacc += fex2(v[c] - mx);
    float lse2 = mx + flg2(sacc);

    if (final_iter) {
        float4* o4 = (float4*)(outp + (size_t)i * CCH);
        o4[0] = make_float4((v[0]-lse2)*LN2, (v[1]-lse2)*LN2,
                            (v[2]-lse2)*LN2, (v[3]-lse2)*LN2);
        o4[1] = make_float4((v[4]-lse2)*LN2, (v[5]-lse2)*LN2,
                            (v[6]-lse2)*LN2, (v[7]-lse2)*LN2);
    } else {
        float4* o4 = (float4*)(g_logb + (size_t)i * CCH);
        o4[0] = make_float4(v[0]-lse2, v[1]-lse2, v[2]-lse2, v[3]-lse2);
        o4[1] = make_float4(v[4]-lse2, v[5]-lse2, v[6]-lse2, v[7]-lse2);
    }

    float4 z = make_float4(0.f, 0.f, 0.f, 0.f);
    ag[0] = z; ag[1] = z;
}

// ---------------- launch ---------------------------------------------------
extern "C" void kernel_launch(void* const* d_in, const int* in_sizes, int n_in,
                              void* d_out, int out_size) {
    const float* x     = (const float*)d_in[0];
    const int*   ei    = (const int*)  d_in[1];
    const float* ew    = (const float*)d_in[2];
    const float* W1    = (const float*)d_in[4];
    const float* b1    = (const float*)d_in[5];
    const float* W2    = (const float*)d_in[6];
    const float* b2    = (const float*)d_in[7];
    const float* param = (const float*)d_in[8];
    const int* srcp = ei;          // first E2C entries are the undirected srcs
    const int* dstp = ei + EE;     // dst row; first E2C entries pair with srcp
    float* outp = (float*)d_out;

    mlp_kernel<<<(NN + BM - 1) / BM, 256>>>(x, W1, b1, W2, b2);
    init_kernel<<<(NN * CCH + 255) / 256, 256>>>(param);

    for (int it = 0; it < KITER; it++) {
        edge_kernel<<<(E2C + 127) / 128, 128>>>(srcp, dstp, ew, it);
        node_kernel<<<(NN + 127) / 128, 128>>>(outp, it == KITER - 1);
    }
}

// round 17
// speedup vs baseline: 1.5478x; 1.3068x over previous
#include <cuda_runtime.h>
#include <math.h>
#include <stdint.h>

#define NN   50000
#define E2C  400000
#define EE   800000
#define DINC 512
#define DHC  128
#define CCH  8
#define KITER 5

#define LOG2E 1.4426950408889634f
#define LN2   0.6931471805599453f

// ---------------- scratch (device globals; no allocation allowed) ----------
// NOTE: all log-domain state (logb0, logb, agg, msg) is kept in BASE-2.
__device__ __align__(16) float g_logb0[NN * CCH];
__device__ __align__(16) float g_logb [NN * CCH];
__device__ __align__(16) float g_agg  [NN * CCH];
__device__ __align__(16) float g_msg0 [EE * CCH];
__device__ __align__(16) float g_msg1 [EE * CCH];
__device__ __align__(16) float g_logH [CCH * CCH];

// ---------------- fast math helpers ----------------------------------------
__device__ __forceinline__ float fex2(float x) {
    float r; asm("ex2.approx.ftz.f32 %0, %1;" : "=f"(r) : "f"(x)); return r;
}
__device__ __forceinline__ float flg2(float x) {
    float r; asm("lg2.approx.ftz.f32 %0, %1;" : "=f"(r) : "f"(x)); return r;
}
__device__ __forceinline__ void redv4(float* p, float a, float b, float c, float d) {
    asm volatile("red.global.add.v4.f32 [%0], {%1, %2, %3, %4};"
                 :: "l"(p), "f"(a), "f"(b), "f"(c), "f"(d) : "memory");
}
// pack two floats to bf16x2: high half = hi_src, low half = lo_src
__device__ __forceinline__ uint32_t pack_bf2(float hi_src, float lo_src) {
    uint32_t d;
    asm("cvt.rn.bf16x2.f32 %0, %1, %2;" : "=r"(d) : "f"(hi_src), "f"(lo_src));
    return d;
}
// split a bf16x2-packed pair back to the fp32 values of its bf16 halves
__device__ __forceinline__ float bf_lo_f32(uint32_t w) { return __uint_as_float(w << 16); }
__device__ __forceinline__ float bf_hi_f32(uint32_t w) { return __uint_as_float(w & 0xFFFF0000u); }

__device__ __forceinline__ void mma_bf16(float4& d, const uint32_t* a, const uint32_t* b) {
    asm("mma.sync.aligned.m16n8k16.row.col.f32.bf16.bf16.f32 "
        "{%0,%1,%2,%3},{%4,%5,%6,%7},{%8,%9},{%0,%1,%2,%3};"
        : "+f"(d.x), "+f"(d.y), "+f"(d.z), "+f"(d.w)
        : "r"(a[0]), "r"(a[1]), "r"(a[2]), "r"(a[3]), "r"(b[0]), "r"(b[1]));
}

// ---------------- MLP: logb0_2 = log2_softmax(relu(x@W1+b1)@W2+b2) ---------
// GEMM1 on tensor cores (bf16 m16n8k16, 3-term hi/lo split for ~fp32 accuracy).
// Block 64 rows x 128 cols, K chunks of 16 (one mma k-step), 8 warps 32x32.
// Smem holds bf16x2 pair-words:
//   A: [row][kpair] pitch 12 words (8 data + 4 pad) -> frag banks 12g+tg all
//      distinct mod 32.
//   B: [kpair][col] pitch 136 -> frag banks 8tg+g distinct.
#define BM 64
#define BKC 16
#define APW 12                    // words per A row
#define BPW 136                   // words per B kpair row
#define NKCH (DINC / BKC)         // 32

#define OFF_AHI 0
#define OFF_ALO (BM * APW)                       // 768
#define OFF_BHI (2 * BM * APW)                   // 1536
#define OFF_BLO (OFF_BHI + 8 * BPW)              // 1536 + 1088 = 2624
#define PH1_WORDS (OFF_BLO + 8 * BPW)            // 3712
#define HS_WORDS (BM * 129)                      // 8256
#define BUF_WORDS (HS_WORDS > PH1_WORDS ? HS_WORDS : PH1_WORDS)

__global__ void __launch_bounds__(256) mlp_kernel(const float* __restrict__ x,
                           const float* __restrict__ W1,
                           const float* __restrict__ b1,
                           const float* __restrict__ W2,
                           const float* __restrict__ b2) {
    __shared__ __align__(16) uint32_t buf[BUF_WORDS];
    __shared__ __align__(16) float W2s[DHC * CCH];
    __shared__ float b1s[DHC];

    uint32_t* Ahi = buf + OFF_AHI;
    uint32_t* Alo = buf + OFF_ALO;
    uint32_t* Bhi = buf + OFF_BHI;
    uint32_t* Blo = buf + OFF_BLO;
    float*    Hs  = (float*)buf;     // phase 2: Hs[r][k] pitch 129

    const int tid = threadIdx.x;
    const int wid = tid >> 5;
    const int lane = tid & 31;
    const int block_row = blockIdx.x * BM;

#pragma unroll
    for (int i = 0; i < 4; i++) W2s[tid + i * 256] = W2[tid + i * 256];
    if (tid < DHC) b1s[tid] = b1[tid];

    // A global load: 64 rows x 16 k -> one float4 per thread
    const int arow = tid >> 2;
    const int aq   = (tid & 3) * 4;            // k offset: 0,4,8,12
    const int kp0  = (tid & 3) * 2;            // kpair word index: 0,2,4,6
    const int gr   = block_row + arow;
    const bool avalid = (gr < NN);

    // B global load: thread group r=tid>>5 loads W1 rows (k0+2r, k0+2r+1), 4 cols
    const int brr  = tid >> 5;                 // 0..7 = kpair row
    const int bcol = (tid & 31) * 4;

    const int m0 = (wid & 1) * 32;
    const int n0 = (wid >> 1) * 32;
    const int g  = lane >> 2;
    const int tg = lane & 3;

    float4 acc[2][4];
#pragma unroll
    for (int mi = 0; mi < 2; mi++)
#pragma unroll
        for (int ni = 0; ni < 4; ni++) acc[mi][ni] = make_float4(0.f, 0.f, 0.f, 0.f);

    float4 ax = make_float4(0.f, 0.f, 0.f, 0.f), bx0, bx1;
    if (avalid) ax = *(const float4*)&x[(size_t)gr * DINC + aq];
    bx0 = *(const float4*)&W1[(size_t)(2 * brr)     * DHC + bcol];
    bx1 = *(const float4*)&W1[(size_t)(2 * brr + 1) * DHC + bcol];

    for (int c = 0; c < NKCH; c++) {
        // ---- A: hi/lo bf16 split, pair-packed store (2 words/thread) ----
        {
            uint32_t h0 = pack_bf2(ax.y, ax.x);           // {hi=k+1, lo=k}
            uint32_t h1 = pack_bf2(ax.w, ax.z);
            float l0e = ax.x - bf_lo_f32(h0), l0o = ax.y - bf_hi_f32(h0);
            float l1e = ax.z - bf_lo_f32(h1), l1o = ax.w - bf_hi_f32(h1);
            *(uint2*)&Ahi[arow * APW + kp0] = make_uint2(h0, h1);
            *(uint2*)&Alo[arow * APW + kp0] = make_uint2(pack_bf2(l0o, l0e),
                                                         pack_bf2(l1o, l1e));
        }
        // ---- B: hi/lo split, word j = {W1[2r+1][col+j] hi, W1[2r][col+j] lo} ----
        {
            float e[4] = {bx0.x, bx0.y, bx0.z, bx0.w};    // even k row
            float o[4] = {bx1.x, bx1.y, bx1.z, bx1.w};    // odd  k row
            uint32_t hw[4], lw[4];
#pragma unroll
            for (int j = 0; j < 4; j++) {
                hw[j] = pack_bf2(o[j], e[j]);
                lw[j] = pack_bf2(o[j] - bf_hi_f32(hw[j]), e[j] - bf_lo_f32(hw[j]));
            }
            *(uint4*)&Bhi[brr * BPW + bcol] = *(uint4*)hw;
            *(uint4*)&Blo[brr * BPW + bcol] = *(uint4*)lw;
        }
        __syncthreads();

        if (c + 1 < NKCH) {
            int k0 = (c + 1) * BKC;
            if (avalid) ax = *(const float4*)&x[(size_t)gr * DINC + k0 + aq];
            bx0 = *(const float4*)&W1[(size_t)(k0 + 2 * brr)     * DHC + bcol];
            bx1 = *(const float4*)&W1[(size_t)(k0 + 2 * brr + 1) * DHC + bcol];
        }

        // ---- one m16n8k16 k-step ----
        {
            uint32_t ah[2][4], al[2][4];
#pragma unroll
            for (int mi = 0; mi < 2; mi++) {
                int b0 = (m0 + 16 * mi + g) * APW;
                ah[mi][0] = Ahi[b0 + tg];          ah[mi][1] = Ahi[b0 + 96 + tg];
                ah[mi][2] = Ahi[b0 + tg + 4];      ah[mi][3] = Ahi[b0 + 96 + tg + 4];
                al[mi][0] = Alo[b0 + tg];          al[mi][1] = Alo[b0 + 96 + tg];
                al[mi][2] = Alo[b0 + tg + 4];      al[mi][3] = Alo[b0 + 96 + tg + 4];
            }
            uint32_t bh[4][2], bl[4][2];
#pragma unroll
            for (int ni = 0; ni < 4; ni++) {
                int bidx = tg * BPW + n0 + 8 * ni + g;
                bh[ni][0] = Bhi[bidx]; bh[ni][1] = Bhi[bidx + 4 * BPW];
                bl[ni][0] = Blo[bidx]; bl[ni][1] = Blo[bidx + 4 * BPW];
            }
#pragma unroll
            for (int mi = 0; mi < 2; mi++)
#pragma unroll
                for (int ni = 0; ni < 4; ni++) {
                    mma_bf16(acc[mi][ni], ah[mi], bh[ni]);
                    mma_bf16(acc[mi][ni], ah[mi], bl[ni]);
                    mma_bf16(acc[mi][ni], al[mi], bh[ni]);
                }
        }
        __syncthreads();
    }

    // epilogue: h = relu(acc + b1) -> Hs
#pragma unroll
    for (int mi = 0; mi < 2; mi++) {
#pragma unroll
        for (int ni = 0; ni < 4; ni++) {
            int row = m0 + 16 * mi + g;
            int col = n0 + 8 * ni + 2 * tg;
            float bb0 = b1s[col], bb1 = b1s[col + 1];
            float v0 = acc[mi][ni].x + bb0, v1 = acc[mi][ni].y + bb1;
            float v2 = acc[mi][ni].z + bb0, v3 = acc[mi][ni].w + bb1;
            Hs[row * 129 + col]           = v0 > 0.f ? v0 : 0.f;
            Hs[row * 129 + col + 1]       = v1 > 0.f ? v1 : 0.f;
            Hs[(row + 8) * 129 + col]     = v2 > 0.f ? v2 : 0.f;
            Hs[(row + 8) * 129 + col + 1] = v3 > 0.f ? v3 : 0.f;
        }
    }
    __syncthreads();

    // second layer + BASE-2 log_softmax: 2 threads per row, 4 channels each
    if (tid < 2 * BM) {
        int row = tid >> 1;
        int ch0 = (tid & 1) * 4;
        int grr = block_row + row;
        if (grr < NN) {
            float lg[4] = {b2[ch0], b2[ch0 + 1], b2[ch0 + 2], b2[ch0 + 3]};
            for (int k = 0; k < DHC; k++) {
                float h = Hs[row * 129 + k];
                const float4 w4 = *(const float4*)&W2s[k * CCH + ch0];
                lg[0] = fmaf(h, w4.x, lg[0]);
                lg[1] = fmaf(h, w4.y, lg[1]);
                lg[2] = fmaf(h, w4.z, lg[2]);
                lg[3] = fmaf(h, w4.w, lg[3]);
            }
            float mx = fmaxf(fmaxf(lg[0], lg[1]), fmaxf(lg[2], lg[3]));
            mx = fmaxf(mx, __shfl_xor_sync(0xFFFFFFFF, mx, 1));
            float y2[4];
            float s = 0.f;
#pragma unroll
            for (int cc = 0; cc < 4; cc++) {
                y2[cc] = (lg[cc] - mx) * LOG2E;
                s += fex2(y2[cc]);
            }
            s += __shfl_xor_sync(0xFFFFFFFF, s, 1);
            float lse2 = flg2(s);
#pragma unroll
            for (int cc = 0; cc < 4; cc++)
                g_logb0[grr * CCH + ch0 + cc] = y2[cc] - lse2;   // base-2
        }
    }
}

// ---------------- init: zero agg + logH = logsigmoid(param + param^T) ------
__global__ void init_kernel(const float* __restrict__ param) {
    int i = blockIdx.x * blockDim.x + threadIdx.x;
    if (i < NN * CCH) g_agg[i] = 0.f;
    if (blockIdx.x == 0 && threadIdx.x < CCH * CCH) {
        int t = threadIdx.x;
        int r = t >> 3, c = t & 7;
        float z = param[r * CCH + c] + param[c * CCH + r];
        float a = fabsf(z);
        g_logH[t] = fminf(z, 0.f) - log1pf(expf(-a));
    }
}

// ---------------- edge kernel: one thread per UNDIRECTED edge --------------
// Base-2 domain; unnormalized messages (per-edge shifts cancel exactly under
// per-node belief normalization). G symmetric -> 36 exp2 instead of 64.
__global__ void edge_kernel(const int* __restrict__ srcp,
                            const int* __restrict__ dstp,
                            const float* __restrict__ wp,
                            int iter) {
    __shared__ float H2s[CCH * CCH];   // logH * log2(e)
    if (threadIdx.x < CCH * CCH) H2s[threadIdx.x] = g_logH[threadIdx.x] * LOG2E;
    __syncthreads();

    int u = blockIdx.x * blockDim.x + threadIdx.x;
    if (u >= E2C) return;

    const float* logb = (iter == 0) ? g_logb0 : g_logb;
    const float* prev = (iter & 1) ? g_msg0 : g_msg1;
    float* cur = (iter & 1) ? g_msg1 : g_msg0;

    int s = srcp[u];
    int d = dstp[u];
    float w = wp[u];

    float xs[8], xd[8];
    {
        const float4* bp = (const float4*)(logb + (size_t)s * CCH);
        float4 v0 = bp[0], v1 = bp[1];
        xs[0]=v0.x; xs[1]=v0.y; xs[2]=v0.z; xs[3]=v0.w;
        xs[4]=v1.x; xs[5]=v1.y; xs[6]=v1.z; xs[7]=v1.w;
        const float4* bq = (const float4*)(logb + (size_t)d * CCH);
        float4 u0 = bq[0], u1 = bq[1];
        xd[0]=u0.x; xd[1]=u0.y; xd[2]=u0.z; xd[3]=u0.w;
        xd[4]=u1.x; xd[5]=u1.y; xd[6]=u1.z; xd[7]=u1.w;
    }
    if (iter != 0) {
        const float4* pf = (const float4*)(prev + (size_t)(u + E2C) * CCH);
        float4 p0 = pf[0], p1 = pf[1];
        xs[0]-=p0.x; xs[1]-=p0.y; xs[2]-=p0.z; xs[3]-=p0.w;
        xs[4]-=p1.x; xs[5]-=p1.y; xs[6]-=p1.z; xs[7]-=p1.w;
        const float4* pb = (const float4*)(prev + (size_t)u * CCH);
        float4 q0 = pb[0], q1 = pb[1];
        xd[0]-=q0.x; xd[1]-=q0.y; xd[2]-=q0.z; xd[3]-=q0.w;
        xd[4]-=q1.x; xd[5]-=q1.y; xd[6]-=q1.z; xd[7]-=q1.w;
    }

    float mxs = xs[0], mxd = xd[0];
#pragma unroll
    for (int c = 1; c < 8; c++) { mxs = fmaxf(mxs, xs[c]); mxd = fmaxf(mxd, xd[c]); }

    float Ef[8], Eb[8];
#pragma unroll
    for (int c = 0; c < 8; c++) {
        Ef[c] = fex2(xs[c] - mxs);
        Eb[c] = fex2(xd[c] - mxd);
    }

    float Sf[8], Sb[8];
#pragma unroll
    for (int c = 0; c < 8; c++) {
        float gg = fex2(w * H2s[c * 8 + c]);
        Sf[c] = Ef[c] * gg;
        Sb[c] = Eb[c] * gg;
    }
#pragma unroll
    for (int c = 1; c < 8; c++) {
#pragma unroll
        for (int cp = 0; cp < c; cp++) {
            float gg = fex2(w * H2s[cp * 8 + c]);
            Sf[c]  = fmaf(Ef[cp], gg, Sf[c]);
            Sf[cp] = fmaf(Ef[c],  gg, Sf[cp]);
            Sb[c]  = fmaf(Eb[cp], gg, Sb[c]);
            Sb[cp] = fmaf(Eb[c],  gg, Sb[cp]);
        }
    }

    float mf[8], mb[8];
#pragma unroll
    for (int c = 0; c < 8; c++) {
        mf[c] = flg2(Sf[c]) + mxs;
        mb[c] = flg2(Sb[c]) + mxd;
    }

    float4* cf = (float4*)(cur + (size_t)u * CCH);
    cf[0] = make_float4(mf[0], mf[1], mf[2], mf[3]);
    cf[1] = make_float4(mf[4], mf[5], mf[6], mf[7]);
    float4* cb = (float4*)(cur + (size_t)(u + E2C) * CCH);
    cb[0] = make_float4(mb[0], mb[1], mb[2], mb[3]);
    cb[1] = make_float4(mb[4], mb[5], mb[6], mb[7]);

    float* agd = g_agg + (size_t)d * CCH;
    redv4(agd,     mf[0], mf[1], mf[2], mf[3]);
    redv4(agd + 4, mf[4], mf[5], mf[6], mf[7]);
    float* ags = g_agg + (size_t)s * CCH;
    redv4(ags,     mb[0], mb[1], mb[2], mb[3]);
    redv4(ags + 4, mb[4], mb[5], mb[6], mb[7]);
}

// ---------------- node kernel: normalize beliefs (base-2), reset agg -------
__global__ void node_kernel(float* __restrict__ outp, int final_iter) {
    int i = blockIdx.x * blockDim.x + threadIdx.x;
    if (i >= NN) return;

    const float4* b0 = (const float4*)(g_logb0 + (size_t)i * CCH);
    float4* ag = (float4*)(g_agg + (size_t)i * CCH);
    float4 a0 = b0[0], a1 = b0[1];
    float4 g0 = ag[0], g1 = ag[1];

    float v[8] = {a0.x + g0.x, a0.y + g0.y, a0.z + g0.z, a0.w + g0.w,
                  a1.x + g1.x, a1.y + g1.y, a1.z + g1.z, a1.w + g1.w};

    float mx = v[0];
#pragma unroll
    for (int c = 1; c < 8; c++) mx = fmaxf(mx, v[c]);
    float sacc = 0.f;
#pragma unroll
    for (int c = 0; c < 8; c++) sacc += fex2(v[c] - mx);
    float lse2 = mx + flg2(sacc);

    if (final_iter) {
        float4* o4 = (float4*)(outp + (size_t)i * CCH);
        o4[0] = make_float4((v[0]-lse2)*LN2, (v[1]-lse2)*LN2,
                            (v[2]-lse2)*LN2, (v[3]-lse2)*LN2);
        o4[1] = make_float4((v[4]-lse2)*LN2, (v[5]-lse2)*LN2,
                            (v[6]-lse2)*LN2, (v[7]-lse2)*LN2);
    } else {
        float4* o4 = (float4*)(g_logb + (size_t)i * CCH);
        o4[0] = make_float4(v[0]-lse2, v[1]-lse2, v[2]-lse2, v[3]-lse2);
        o4[1] = make_float4(v[4]-lse2, v[5]-lse2, v[6]-lse2, v[7]-lse2);
    }

    float4 z = make_float4(0.f, 0.f, 0.f, 0.f);
    ag[0] = z; ag[1] = z;
}

// ---------------- launch ---------------------------------------------------
extern "C" void kernel_launch(void* const* d_in, const int* in_sizes, int n_in,
                              void* d_out, int out_size) {
    const float* x     = (const float*)d_in[0];
    const int*   ei    = (const int*)  d_in[1];
    const float* ew    = (const float*)d_in[2];
    const float* W1    = (const float*)d_in[4];
    const float* b1    = (const float*)d_in[5];
    const float* W2    = (const float*)d_in[6];
    const float* b2    = (const float*)d_in[7];
    const float* param = (const float*)d_in[8];
    const int* srcp = ei;          // first E2C entries are the undirected srcs
    const int* dstp = ei + EE;     // dst row; first E2C entries pair with srcp
    float* outp = (float*)d_out;

    mlp_kernel<<<(NN + BM - 1) / BM, 256>>>(x, W1, b1, W2, b2);
    init_kernel<<<(NN * CCH + 255) / 256, 256>>>(param);

    for (int it = 0; it < KITER; it++) {
        edge_kernel<<<(E2C + 127) / 128, 128>>>(srcp, dstp, ew, it);
        node_kernel<<<(NN + 127) / 128, 128>>>(outp, it == KITER - 1);
    }
}